// round 2
// baseline (speedup 1.0000x reference)
#include <cuda_runtime.h>
#include <cstdint>

// out[dst] += x[src] for each edge. x: [N, 64] f32.
// edge_index: [2, E] — int32 on device (JAX x64 disabled downcasts int64->int32).
// 16 threads per edge, one float4 quad each; gather via __ldg (x = 12.8MB,
// L2-resident), reduce via red.global.add.v4.f32 (vector no-return atomic).

__global__ void mp_zero_kernel(float4* __restrict__ out, int n4) {
    int i = blockIdx.x * blockDim.x + threadIdx.x;
    if (i < n4) out[i] = make_float4(0.f, 0.f, 0.f, 0.f);
}

__global__ void mp_scatter_kernel(const float4* __restrict__ x,
                                  const int* __restrict__ ei,
                                  float* __restrict__ out,
                                  int E) {
    int idx = blockIdx.x * blockDim.x + threadIdx.x;
    int e = idx >> 4;        // edge id
    int q = idx & 15;        // which float4 quad of the 64-float row
    if (e >= E) return;

    int src = __ldg(ei + e);        // row 0 of edge_index
    int dst = __ldg(ei + E + e);    // row 1 of edge_index

    float4 v = __ldg(x + src * 16 + q);

    float* p = out + dst * 64 + q * 4;   // 16B-aligned
    asm volatile("red.global.add.v4.f32 [%0], {%1, %2, %3, %4};"
                 :: "l"(p), "f"(v.x), "f"(v.y), "f"(v.z), "f"(v.w)
                 : "memory");
}

extern "C" void kernel_launch(void* const* d_in, const int* in_sizes, int n_in,
                              void* d_out, int out_size) {
    const float4* x = (const float4*)d_in[0];
    const int* ei = (const int*)d_in[1];
    float* out = (float*)d_out;

    int E = in_sizes[1] / 2;          // 800000
    int n4 = out_size / 4;            // output float4 count

    {
        int threads = 256;
        int blocks = (n4 + threads - 1) / threads;
        mp_zero_kernel<<<blocks, threads>>>((float4*)out, n4);
    }
    {
        long long work = (long long)E * 16;
        int threads = 256;
        int blocks = (int)((work + threads - 1) / threads);
        mp_scatter_kernel<<<blocks, threads>>>(x, ei, out, E);
    }
}

// round 3
// speedup vs baseline: 1.0520x; 1.0520x over previous
#include <cuda_runtime.h>
#include <cstdint>

// out[dst] += x[src]. x: [N,64] f32, edge_index: [2,E] int32 on device.
// 16 threads per edge-pair-quad: each thread owns one float4 quad of TWO
// consecutive edges (unroll 2) -> doubled MLP per thread, halved redundant
// index loads. Gather via __ldg (x L2-resident), reduce via
// red.global.add.v4.f32.

__global__ void mp_zero_kernel(float4* __restrict__ out, int n4) {
    int i = blockIdx.x * blockDim.x + threadIdx.x;
    if (i < n4) out[i] = make_float4(0.f, 0.f, 0.f, 0.f);
}

__device__ __forceinline__ void red_add_v4(float* p, float4 v) {
    asm volatile("red.global.add.v4.f32 [%0], {%1, %2, %3, %4};"
                 :: "l"(p), "f"(v.x), "f"(v.y), "f"(v.z), "f"(v.w)
                 : "memory");
}

__global__ void mp_scatter_kernel(const float4* __restrict__ x,
                                  const int* __restrict__ ei,
                                  float* __restrict__ out,
                                  int E) {
    int idx = blockIdx.x * blockDim.x + threadIdx.x;
    int q  = idx & 15;          // quad within the 64-float row
    int g  = idx >> 4;          // edge-pair id
    int e0 = g * 2;
    if (e0 >= E) return;
    int e1 = e0 + 1;

    // Issue both index loads up front (independent).
    int src0 = __ldg(ei + e0);
    int dst0 = __ldg(ei + E + e0);
    bool has1 = (e1 < E);
    int src1 = has1 ? __ldg(ei + e1) : src0;
    int dst1 = has1 ? __ldg(ei + E + e1) : dst0;

    // Two independent gathers in flight.
    float4 v0 = __ldg(x + src0 * 16 + q);
    float4 v1 = __ldg(x + src1 * 16 + q);

    red_add_v4(out + dst0 * 64 + q * 4, v0);
    if (has1) red_add_v4(out + dst1 * 64 + q * 4, v1);
}

extern "C" void kernel_launch(void* const* d_in, const int* in_sizes, int n_in,
                              void* d_out, int out_size) {
    const float4* x = (const float4*)d_in[0];
    const int* ei = (const int*)d_in[1];
    float* out = (float*)d_out;

    int E = in_sizes[1] / 2;          // 800000
    int n4 = out_size / 4;

    {
        int threads = 256;
        int blocks = (n4 + threads - 1) / threads;
        mp_zero_kernel<<<blocks, threads>>>((float4*)out, n4);
    }
    {
        long long pairs = (E + 1) / 2;
        long long work = pairs * 16;
        int threads = 256;
        int blocks = (int)((work + threads - 1) / threads);
        mp_scatter_kernel<<<blocks, threads>>>(x, ei, out, E);
    }
}